// round 14
// baseline (speedup 1.0000x reference)
#include <cuda_runtime.h>
#include <math.h>

#define RESX   128
#define NVOX   (RESX*RESX*RESX)
#define NRAYS  1024
#define NS     891

#define ACT_SHIFT (-4.5951198501345898f)

// ---------------- global scratch ----------------
__device__ float g_norm[3*NVOX];
__device__ float g_w[NRAYS*NS];
__device__ float g_T[NRAYS];
__device__ float g_tmin[NRAYS];
__device__ float g_invn[NRAYS];
__device__ int   g_sstart[NRAYS];
__device__ int   g_scnt[NRAYS];
__device__ int   g_base[NRAYS+1];
__device__ int   g_work;
__device__ float g_c0[NRAYS*NS];
__device__ float g_c1[NRAYS*NS];
__device__ float g_c2[NRAYS*NS];

// ---------------------------------------------------------------------------
// packed fp32x2 helpers
// ---------------------------------------------------------------------------
typedef unsigned long long u64;
__device__ __forceinline__ u64 f2pack(float lo, float hi){
    u64 r; asm("mov.b64 %0,{%1,%2};" : "=l"(r) : "f"(lo), "f"(hi)); return r;
}
__device__ __forceinline__ void f2unpack(u64 v, float& lo, float& hi){
    asm("mov.b64 {%0,%1},%2;" : "=f"(lo), "=f"(hi) : "l"(v));
}
__device__ __forceinline__ u64 ffma2(u64 a, u64 b, u64 c){
    u64 d; asm("fma.rn.f32x2 %0,%1,%2,%3;" : "=l"(d) : "l"(a), "l"(b), "l"(c)); return d;
}

__device__ __forceinline__ void tri_setup(float px, float py, float pz,
                                          int* off, float* w)
{
    float ga = (px + 1.f)*0.5f*127.f;
    float gb = (py + 1.f)*0.5f*127.f;
    float gc = (pz + 1.f)*0.5f*127.f;
    float fa0 = floorf(ga), fb0 = floorf(gb), fc0 = floorf(gc);
    float fa = ga - fa0, fb = gb - fb0, fc = gc - fc0;
    int a0 = min(max((int)fa0, 0), 127);
    int b0 = min(max((int)fb0, 0), 127);
    int c0 = min(max((int)fc0, 0), 127);
    int a1 = min(a0+1, 127), b1 = min(b0+1, 127), c1 = min(c0+1, 127);
    int A0 = a0*16384, A1 = a1*16384, B0 = b0*128, B1 = b1*128;
    off[0]=A0+B0+c0; off[1]=A0+B0+c1; off[2]=A0+B1+c0; off[3]=A0+B1+c1;
    off[4]=A1+B0+c0; off[5]=A1+B0+c1; off[6]=A1+B1+c0; off[7]=A1+B1+c1;
    float wa0 = 1.f-fa, wb0 = 1.f-fb, wc0 = 1.f-fc;
    w[0]=wa0*wb0*wc0; w[1]=wa0*wb0*fc; w[2]=wa0*fb*wc0; w[3]=wa0*fb*fc;
    w[4]=fa*wb0*wc0;  w[5]=fa*wb0*fc;  w[6]=fa*fb*wc0;  w[7]=fa*fb*fc;
}

// ---------------------------------------------------------------------------
// Kernel 1: FUSED conv (blocks 0..1023, 8-wide a-blocking, pre-packed taps)
// + prep (1024..2047, parallel transmittance scan + g_work reset).
// ---------------------------------------------------------------------------
#define CONV_BLOCKS 1024
__global__ void __launch_bounds__(256) fused_kernel(
    const float* __restrict__ dens, const float* __restrict__ kern,
    const float* __restrict__ ro,   const float* __restrict__ rdv)
{
    __shared__ float smem_u[12*12*36];    // conv tile 5184; prep: aw (891)
    __shared__ u64   skp[375];
    __shared__ float s_wprod[8];
    __shared__ int s_min, s_max;

    if (blockIdx.x < CONV_BLOCKS){
        // ----------------- conv path: 8 outputs along a per thread -------
        float* tile = smem_u;
        int bid = blockIdx.x;
        int tc = threadIdx.x & 31;
        int tb = threadIdx.x >> 5;
        int tid = threadIdx.x;
        int c0 = (bid & 3)*32;
        int b0 = ((bid >> 2) & 15)*8;
        int a0 = (bid >> 6)*8;

        for (int i=tid; i<375; i+=256){
            float k = kern[i];
            skp[i] = f2pack(k, k);
        }
        for (int i=tid; i<12*12*36; i+=256){
            int ic = i % 36; int r = i / 36; int ib = r % 12; int ia = r / 12;
            int ga = a0 - 2 + ia, gb = b0 - 2 + ib, gc = c0 - 2 + ic;
            float v = 0.f;
            if ((unsigned)ga < 128u && (unsigned)gb < 128u && (unsigned)gc < 128u)
                v = dens[(ga*128 + gb)*128 + gc];
            tile[i] = v;
        }
        __syncthreads();

        u64 s0p[4]={0,0,0,0}, s1p[4]={0,0,0,0}, s2p[4]={0,0,0,0};
        for (int db=0; db<5; db++){
            for (int dc=0; dc<5; dc++){
                float tv[12];
                #pragma unroll
                for (int ia=0; ia<12; ia++)
                    tv[ia] = tile[(ia*12 + tb + db)*36 + tc + dc];
                u64 p[11];
                #pragma unroll
                for (int i=0; i<11; i++) p[i] = f2pack(tv[i], tv[i+1]);
                #pragma unroll
                for (int da=0; da<5; da++){
                    u64 kp0 = skp[        da*25 + db*5 + dc];
                    u64 kp1 = skp[125 +   da*25 + db*5 + dc];
                    u64 kp2 = skp[250 +   da*25 + db*5 + dc];
                    #pragma unroll
                    for (int v=0; v<4; v++){
                        s0p[v] = ffma2(kp0, p[da + 2*v], s0p[v]);
                        s1p[v] = ffma2(kp1, p[da + 2*v], s1p[v]);
                        s2p[v] = ffma2(kp2, p[da + 2*v], s2p[v]);
                    }
                }
            }
        }
        float s0[8], s1[8], s2[8];
        #pragma unroll
        for (int v=0; v<4; v++){
            f2unpack(s0p[v], s0[2*v], s0[2*v+1]);
            f2unpack(s1p[v], s1[2*v], s1[2*v+1]);
            f2unpack(s2p[v], s2[2*v], s2[2*v+1]);
        }
        #pragma unroll
        for (int v=0; v<8; v++){
            int idx = ((a0+v)*128 + (b0+tb))*128 + (c0+tc);
            float n0 = s0[v], n1 = s1[v], n2 = s2[v];
            float len = sqrtf(n0*n0 + n1*n1 + n2*n2);
            float inv = -1.f / fmaxf(len, 1e-12f);
            g_norm[idx]          = n0*inv;
            g_norm[NVOX + idx]   = n1*inv;
            g_norm[2*NVOX + idx] = n2*inv;
        }
    } else {
        // ----------------- prep path -----------------
        float* aw = smem_u;
        int tid = threadIdx.x;
        int lane = tid & 31, wid = tid >> 5;
        int rid = blockIdx.x - CONV_BLOCKS;
        if (tid == 0){
            s_min = 0x7fffffff; s_max = -1;
            if (rid == 0) g_work = 0;      // reset work-steal counter for mlp
        }
        __syncthreads();

        float ox = ro[rid*3+0], oy = ro[rid*3+1], oz = ro[rid*3+2];
        float dx = rdv[rid*3+0], dy = rdv[rid*3+1], dz = rdv[rid*3+2];

        float vecx = (dx == 0.f) ? 1e-6f : dx;
        float vecy = (dy == 0.f) ? 1e-6f : dy;
        float vecz = (dz == 0.f) ? 1e-6f : dz;
        float rax = ( 1.f - ox)/vecx, rbx = (-1.f - ox)/vecx;
        float ray_ = ( 1.f - oy)/vecy, rby = (-1.f - oy)/vecy;
        float raz = ( 1.f - oz)/vecz, rbz = (-1.f - oz)/vecz;
        float tmin = fmaxf(fmaxf(fminf(rax,rbx), fminf(ray_,rby)), fminf(raz,rbz));
        tmin = fminf(fmaxf(tmin, 0.2f), 3.0f);
        float tmax = fminf(fminf(fmaxf(rax,rbx), fmaxf(ray_,rby)), fmaxf(raz,rbz));
        tmax = fminf(fmaxf(tmax, 0.2f), 3.0f);
        bool maskray = (tmax <= tmin);
        float invn = 1.f / sqrtf(dx*dx + dy*dy + dz*dz);

        int lmin = 0x7fffffff, lmax = -1;
        for (int s=tid; s<NS; s+=256){
            float t  = tmin + (0.0078125f * (float)s) * invn;
            float px = fmaf(dx, t, ox), py = fmaf(dy, t, oy), pz = fmaf(dz, t, oz);
            bool in = (!maskray) &&
                      !(px < -1.f || px > 1.f || py < -1.f || py > 1.f || pz < -1.f || pz > 1.f);
            float a = 0.f;
            if (in){
                int off[8]; float wc[8];
                tri_setup(px, py, pz, off, wc);
                float l0 = 0.f;
                #pragma unroll
                for (int k=0; k<8; k++) l0 = fmaf(wc[k], __ldg(dens + off[k]), l0);
                float xs = l0 + ACT_SHIFT;
                float sp = fmaxf(xs, 0.f) + log1pf(expf(-fabsf(xs)));
                a = 1.f - expf(-sp*0.5f);
                lmin = min(lmin, s); lmax = max(lmax, s);
            }
            aw[s] = a;
        }
        if (lmax >= 0){ atomicMin(&s_min, lmin); atomicMax(&s_max, lmax); }
        __syncthreads();

        // parallel transmittance scan: 4 contiguous samples / thread
        int base4 = tid*4;
        float lp = 1.f;
        #pragma unroll
        for (int j=0; j<4; j++){
            int s = base4 + j;
            if (s < NS) lp *= fmaxf(1.f - aw[s], 1e-10f);
        }
        float v = lp;
        #pragma unroll
        for (int o=1; o<32; o<<=1){
            float n = __shfl_up_sync(0xffffffffu, v, o);
            if (lane >= o) v *= n;
        }
        if (lane == 31) s_wprod[wid] = v;
        __syncthreads();
        float warp_excl = 1.f;
        #pragma unroll
        for (int wj=0; wj<8; wj++)
            if (wj < wid) warp_excl *= s_wprod[wj];
        float vexcl = __shfl_up_sync(0xffffffffu, v, 1);
        if (lane == 0) vexcl = 1.f;
        float T = warp_excl * vexcl;

        int smn = s_min, smx = s_max;
        #pragma unroll
        for (int j=0; j<4; j++){
            int s = base4 + j;
            if (s < NS){
                float a = aw[s];
                if (s >= smn && s <= smx)
                    g_w[rid*NS + s] = a * T;
                T *= fmaxf(1.f - a, 1e-10f);
            }
        }

        if (tid == 0){
            float Tall = 1.f;
            #pragma unroll
            for (int wj=0; wj<8; wj++) Tall *= s_wprod[wj];
            g_T[rid]    = Tall;
            g_tmin[rid] = tmin;
            g_invn[rid] = invn;
            int cnt = (smx >= smn) ? (smx - smn + 1) : 0;
            g_sstart[rid] = (cnt > 0) ? smn : 0;
            g_scnt[rid]   = cnt;
        }
    }
}

// ---------------------------------------------------------------------------
// Kernel 2: QUAD-split MLP. 4 lanes per quad handle 4 samples; each thread
// owns 16 neurons for all 4 samples -> each weight LDS.128 feeds 8 FFMA2.
// Per-block local prefix scan replaces the separate scan kernel.
// ---------------------------------------------------------------------------
// shared layout (float offsets); weight rows: 80 floats = 4 chunks x 20 (16+4 pad)
#define OFF_W0    0            // 54*80 = 4320
#define OFF_W1    4320         // 64*80 = 5120
#define OFF_W2    9440         // 5120
#define OFF_W3    14560        // 192
#define OFF_B0    14752
#define OFF_B1    14816
#define OFF_B2    14880
#define OFF_B3    14944        // 3 (+1 pad)
#define OFF_BASE  14948        // 1025 ints -> 15973, pad 15976
#define OFF_STAGE 15976
#define QS        276          // per-quad stage stride (4 chunks x 68 + 4 pad)
#define MLP_NTH   384
#define SH_FLOATS (OFF_STAGE + (MLP_NTH/4)*QS)
#define SMEM_MLP  (SH_FLOATS*4)
#define MLP_BLOCKS 148

__device__ __forceinline__ void bias_quad(u64* h, const float* bias, int nc){
    const u64* bp = (const u64*)bias;
    #pragma unroll
    for (int t=0; t<8; t++){
        u64 bb = bp[nc*8 + t];
        h[t]=bb; h[8+t]=bb; h[16+t]=bb; h[24+t]=bb;
    }
}

template<int R>
__device__ __forceinline__ void gemv_quad(u64* h, const float* wb, const float* fp){
    int r = 0;
    #pragma unroll
    for (int c=0; c<4; c++){
        const int jmax = (R - c*16) > 16 ? 16 : (R - c*16);
        if (jmax <= 0) break;
        const float* fpc = fp + c*68;
        #pragma unroll 8
        for (int j=0; j<jmax; j++, r++){
            float4 v4 = *(const float4*)(fpc + j*4);
            u64 vv0 = f2pack(v4.x, v4.x);
            u64 vv1 = f2pack(v4.y, v4.y);
            u64 vv2 = f2pack(v4.z, v4.z);
            u64 vv3 = f2pack(v4.w, v4.w);
            const ulonglong2* wr = (const ulonglong2*)(wb + r*80);
            #pragma unroll
            for (int k=0; k<4; k++){
                ulonglong2 w2 = wr[k];
                h[2*k]      = ffma2(vv0, w2.x, h[2*k]);
                h[2*k+1]    = ffma2(vv0, w2.y, h[2*k+1]);
                h[8+2*k]    = ffma2(vv1, w2.x, h[8+2*k]);
                h[8+2*k+1]  = ffma2(vv1, w2.y, h[8+2*k+1]);
                h[16+2*k]   = ffma2(vv2, w2.x, h[16+2*k]);
                h[16+2*k+1] = ffma2(vv2, w2.y, h[16+2*k+1]);
                h[24+2*k]   = ffma2(vv3, w2.x, h[24+2*k]);
                h[24+2*k+1] = ffma2(vv3, w2.y, h[24+2*k+1]);
            }
        }
    }
}

__device__ __forceinline__ void relu_quad(const u64* h, float* fpw){
    #pragma unroll
    for (int t=0; t<8; t++){
        float a0,b0,a1,b1,a2,b2,a3,b3;
        f2unpack(h[t],    a0, b0);
        f2unpack(h[8+t],  a1, b1);
        f2unpack(h[16+t], a2, b2);
        f2unpack(h[24+t], a3, b3);
        float4 r0 = make_float4(fmaxf(a0,0.f), fmaxf(a1,0.f), fmaxf(a2,0.f), fmaxf(a3,0.f));
        float4 r1 = make_float4(fmaxf(b0,0.f), fmaxf(b1,0.f), fmaxf(b2,0.f), fmaxf(b3,0.f));
        *(float4*)(fpw + (2*t)*4)     = r0;
        *(float4*)(fpw + (2*t)*4 + 4) = r1;
    }
}

__global__ void __launch_bounds__(MLP_NTH, 1) mlp_kernel(
    const float* __restrict__ ro,  const float* __restrict__ rdv,
    const float* __restrict__ vdv, const float* __restrict__ grid,
    const float* __restrict__ w0,  const float* __restrict__ b0,
    const float* __restrict__ w1,  const float* __restrict__ b1,
    const float* __restrict__ w2,  const float* __restrict__ b2,
    const float* __restrict__ w3,  const float* __restrict__ b3)
{
    extern __shared__ float sh[];
    __shared__ int swsum[8];
    int tid  = threadIdx.x;
    int lane = tid & 31;
    int nc   = tid & 3;            // neuron chunk AND sample slot in quad
    int qg   = tid >> 2;           // block-local quad id
    int* sbase = (int*)(sh + OFF_BASE);

    // weights into chunked layout: row*80 + (j>>4)*20 + (j&15)
    for (int i=tid; i<54*64; i+=MLP_NTH){
        int r = i>>6, j = i&63;
        sh[OFF_W0 + r*80 + (j>>4)*20 + (j&15)] = w0[i];
    }
    for (int i=tid; i<64*64; i+=MLP_NTH){
        int r = i>>6, j = i&63;
        int dst = r*80 + (j>>4)*20 + (j&15);
        sh[OFF_W1 + dst] = w1[i];
        sh[OFF_W2 + dst] = w2[i];
    }
    for (int i=tid; i<192; i+=MLP_NTH) sh[OFF_W3+i] = w3[i];
    for (int i=tid; i<64;  i+=MLP_NTH){
        sh[OFF_B0+i]=b0[i]; sh[OFF_B1+i]=b1[i]; sh[OFF_B2+i]=b2[i];
    }
    if (tid < 3) sh[OFF_B3+tid] = b3[tid];

    // ---- local prefix scan of g_scnt -> sbase (replaces scan kernel) ----
    int s0=0, s1=0, s2=0, s3=0, vincl=0;
    if (tid < 256){
        int c0v = g_scnt[tid*4+0];
        int c1v = g_scnt[tid*4+1];
        int c2v = g_scnt[tid*4+2];
        int c3v = g_scnt[tid*4+3];
        s0 = c0v; s1 = s0+c1v; s2 = s1+c2v; s3 = s2+c3v;
        vincl = s3;
        #pragma unroll
        for (int o=1; o<32; o<<=1){
            int n = __shfl_up_sync(0xffffffffu, vincl, o);
            if (lane >= o) vincl += n;
        }
        if (lane == 31) swsum[tid>>5] = vincl;
    }
    __syncthreads();
    if (tid < 256){
        int wid8 = tid >> 5;
        int we = 0;
        #pragma unroll
        for (int wj=0; wj<8; wj++) if (wj < wid8) we += swsum[wj];
        int ex = we + vincl - s3;
        sbase[tid*4+1] = ex + s0;
        sbase[tid*4+2] = ex + s1;
        sbase[tid*4+3] = ex + s2;
        sbase[tid*4+4] = ex + s3;
    }
    if (tid == 0) sbase[0] = 0;
    __syncthreads();
    int total = sbase[NRAYS];
    if (blockIdx.x == 0){
        for (int i=tid; i<NRAYS+1; i+=MLP_NTH) g_base[i] = sbase[i];
    }

    int nchunks = (total + 31) >> 5;
    float* fq = sh + OFF_STAGE + qg*QS;
    const float* wl0 = sh + OFF_W0 + nc*20;
    const float* wl1 = sh + OFF_W1 + nc*20;
    const float* wl2 = sh + OFF_W2 + nc*20;

#define FPUT(f_, v_) fq[(((f_)>>4)*68) + (((f_)&15)*4) + nc] = (v_)

    while (true){
        int chunk = 0;
        if (lane == 0) chunk = atomicAdd(&g_work, 1);
        chunk = __shfl_sync(0xffffffffu, chunk, 0);
        if (chunk >= nchunks) break;
        int e = chunk*32 + lane;
        bool valid = (e < total);
        int ec = valid ? e : (total - 1);

        int lo = 0, hi = NRAYS;
        while (hi - lo > 1){
            int mid = (lo + hi) >> 1;
            if (sbase[mid] <= ec) lo = mid; else hi = mid;
        }
        int ray = lo;
        int s = g_sstart[ray] + (ec - sbase[ray]);

        float ox = __ldg(ro+ray*3+0), oy = __ldg(ro+ray*3+1), oz = __ldg(ro+ray*3+2);
        float dx = __ldg(rdv+ray*3+0), dy = __ldg(rdv+ray*3+1), dz = __ldg(rdv+ray*3+2);
        float vx = __ldg(vdv+ray*3+0), vy = __ldg(vdv+ray*3+1), vz = __ldg(vdv+ray*3+2);
        float tmin = __ldg(&g_tmin[ray]);
        float invn = __ldg(&g_invn[ray]);
        float wgt  = __ldg(&g_w[ray*NS + s]);

        float t  = tmin + (0.0078125f * (float)s) * invn;
        float px = fmaf(dx, t, ox), py = fmaf(dy, t, oy), pz = fmaf(dz, t, oz);

        int off[8]; float wc[8];
        tri_setup(px, py, pz, off, wc);

        float nvx[8], nvy[8], nvz[8];
        #pragma unroll
        for (int k=0; k<8; k++){
            nvx[k] = __ldg(g_norm + off[k]);
            nvy[k] = __ldg(g_norm + NVOX + off[k]);
            nvz[k] = __ldg(g_norm + 2*NVOX + off[k]);
        }

        for (int ch=1; ch<=15; ++ch){
            const float* gp = grid + ch*NVOX;
            float v = 0.f;
            #pragma unroll
            for (int k=0; k<8; k++) v = fmaf(wc[k], __ldg(gp + off[k]), v);
            FPUT(ch-1, v);
        }

        float nsx = 0.f, nsy = 0.f, nsz = 0.f;
        #pragma unroll
        for (int k=0; k<8; k++){
            nsx = fmaf(wc[k], nvx[k], nsx);
            nsy = fmaf(wc[k], nvy[k], nsy);
            nsz = fmaf(wc[k], nvz[k], nsz);
        }
        float nl = sqrtf(nsx*nsx + nsy*nsy + nsz*nsz);
        float ninv = -1.f / fmaxf(nl, 1e-12f);
        nsx *= ninv; nsy *= ninv; nsz *= ninv;
        float dt  = -(vx*nsx + vy*nsy + vz*nsz);
        float rx = fmaf(2.f*dt, nsx, vx);
        float ry = fmaf(2.f*dt, nsy, vy);
        float rz = fmaf(2.f*dt, nsz, vz);
        FPUT(15, rx);
        FPUT(16, ry);
        FPUT(17, rz);

        // sin/cos of r*2^f via doubling recurrence (freqs are powers of 2)
        {
            float sv[3], cv3[3];
            sincosf(rx, &sv[0], &cv3[0]);
            sincosf(ry, &sv[1], &cv3[1]);
            sincosf(rz, &sv[2], &cv3[2]);
            #pragma unroll
            for (int f=0; f<6; ++f){
                #pragma unroll
                for (int k3=0; k3<3; k3++){
                    FPUT(18 + f*3 + k3, sv[k3]);
                    FPUT(36 + f*3 + k3, cv3[k3]);
                }
                if (f < 5){
                    #pragma unroll
                    for (int k3=0; k3<3; k3++){
                        float sn = sv[k3], cn = cv3[k3];
                        sv[k3]  = 2.f*sn*cn;
                        cv3[k3] = fmaf(-2.f*sn, sn, 1.f);
                    }
                }
            }
        }
        __syncwarp();

        u64 h[32];
        bias_quad(h, sh + OFF_B0, nc);
        gemv_quad<54>(h, wl0, fq);
        __syncwarp();
        relu_quad(h, fq + nc*68);
        __syncwarp();

        bias_quad(h, sh + OFF_B1, nc);
        gemv_quad<64>(h, wl1, fq);
        __syncwarp();
        relu_quad(h, fq + nc*68);
        __syncwarp();

        bias_quad(h, sh + OFF_B2, nc);
        gemv_quad<64>(h, wl2, fq);

        // layer 3 (64 -> 3): 16-neuron partials for all 4 samples, quad reduce
        float p0[4]={0,0,0,0}, p1[4]={0,0,0,0}, p2[4]={0,0,0,0};
        #pragma unroll
        for (int tt=0; tt<8; tt++){
            int n0 = nc*16 + 2*tt;
            float q00 = sh[OFF_W3 + n0*3 + 0];
            float q01 = sh[OFF_W3 + n0*3 + 1];
            float q02 = sh[OFF_W3 + n0*3 + 2];
            float q10 = sh[OFF_W3 + n0*3 + 3];
            float q11 = sh[OFF_W3 + n0*3 + 4];
            float q12 = sh[OFF_W3 + n0*3 + 5];
            #pragma unroll
            for (int sI=0; sI<4; sI++){
                float a, b;
                f2unpack(h[sI*8 + tt], a, b);
                a = fmaxf(a, 0.f); b = fmaxf(b, 0.f);
                p0[sI] = fmaf(a, q00, fmaf(b, q10, p0[sI]));
                p1[sI] = fmaf(a, q01, fmaf(b, q11, p1[sI]));
                p2[sI] = fmaf(a, q02, fmaf(b, q12, p2[sI]));
            }
        }
        #pragma unroll
        for (int sI=0; sI<4; sI++){
            p0[sI] += __shfl_xor_sync(0xffffffffu, p0[sI], 1);
            p0[sI] += __shfl_xor_sync(0xffffffffu, p0[sI], 2);
            p1[sI] += __shfl_xor_sync(0xffffffffu, p1[sI], 1);
            p1[sI] += __shfl_xor_sync(0xffffffffu, p1[sI], 2);
            p2[sI] += __shfl_xor_sync(0xffffffffu, p2[sI], 1);
            p2[sI] += __shfl_xor_sync(0xffffffffu, p2[sI], 2);
        }
        float c0s = (nc==0 ? p0[0] : nc==1 ? p0[1] : nc==2 ? p0[2] : p0[3]) + sh[OFF_B3+0];
        float c1s = (nc==0 ? p1[0] : nc==1 ? p1[1] : nc==2 ? p1[2] : p1[3]) + sh[OFF_B3+1];
        float c2s = (nc==0 ? p2[0] : nc==1 ? p2[1] : nc==2 ? p2[2] : p2[3]) + sh[OFF_B3+2];
        float col0 = 1.f / (1.f + expf(-c0s));
        float col1 = 1.f / (1.f + expf(-c1s));
        float col2 = 1.f / (1.f + expf(-c2s));
        if (valid){
            g_c0[e] = wgt * col0;
            g_c1[e] = wgt * col1;
            g_c2[e] = wgt * col2;
        }
    }
#undef FPUT
}

// ---------------------------------------------------------------------------
// Kernel 3: per-ray reduction + background. 8 warps/block, 1 warp per ray.
// ---------------------------------------------------------------------------
__global__ void __launch_bounds__(256) reduce_kernel(float* __restrict__ out)
{
    int wrp = threadIdx.x >> 5;
    int lane = threadIdx.x & 31;
    int ray = blockIdx.x*8 + wrp;
    int base = g_base[ray];
    int cnt  = g_base[ray+1] - base;
    float a0 = 0.f, a1 = 0.f, a2 = 0.f;
    for (int i=lane; i<cnt; i+=32){
        a0 += g_c0[base+i];
        a1 += g_c1[base+i];
        a2 += g_c2[base+i];
    }
    #pragma unroll
    for (int o=16; o; o>>=1){
        a0 += __shfl_down_sync(0xffffffffu, a0, o);
        a1 += __shfl_down_sync(0xffffffffu, a1, o);
        a2 += __shfl_down_sync(0xffffffffu, a2, o);
    }
    if (lane == 0){
        float Tf = g_T[ray];
        out[ray*3+0] = a0 + Tf;
        out[ray*3+1] = a1 + Tf;
        out[ray*3+2] = a2 + Tf;
    }
}

extern "C" void kernel_launch(void* const* d_in, const int* in_sizes, int n_in,
                              void* d_out, int out_size)
{
    (void)in_sizes; (void)n_in; (void)out_size;
    const float* ro    = (const float*)d_in[0];
    const float* rd    = (const float*)d_in[1];
    const float* vd    = (const float*)d_in[2];
    const float* grid  = (const float*)d_in[3];
    const float* sobel = (const float*)d_in[4];
    const float* w0 = (const float*)d_in[5];
    const float* b0 = (const float*)d_in[6];
    const float* w1 = (const float*)d_in[7];
    const float* b1 = (const float*)d_in[8];
    const float* w2 = (const float*)d_in[9];
    const float* b2 = (const float*)d_in[10];
    const float* w3 = (const float*)d_in[11];
    const float* b3 = (const float*)d_in[12];
    float* out = (float*)d_out;

    fused_kernel<<<CONV_BLOCKS + NRAYS, 256>>>(grid, sobel, ro, rd);

    static int smem_set = 0;
    if (!smem_set){
        cudaFuncSetAttribute(mlp_kernel,
                             cudaFuncAttributeMaxDynamicSharedMemorySize, SMEM_MLP);
        smem_set = 1;
    }
    mlp_kernel<<<MLP_BLOCKS, MLP_NTH, SMEM_MLP>>>(ro, rd, vd, grid,
                                                  w0, b0, w1, b1, w2, b2, w3, b3);
    reduce_kernel<<<NRAYS/8, 256>>>(out);
}